// round 1
// baseline (speedup 1.0000x reference)
#include <cuda_runtime.h>
#include <cstdint>

#define BB 2
#define SQ 1024
#define SK 1024
#define DD 64
#define DV 64
#define NSPLIT 16
#define KCHUNK (SK / NSPLIT)   // 64
#define QTILE 64               // threads per block = queries per block

typedef unsigned long long ull;

// scratch: partial accumulators [b][split][d][q] and partial l [b][split][q]
__device__ float g_part_acc[(size_t)BB * NSPLIT * DV * SQ];
__device__ float g_part_l[(size_t)BB * NSPLIT * SQ];

__device__ __forceinline__ ull add_f32x2(ull a, ull b) {
    ull r;
    asm("add.rn.f32x2 %0, %1, %2;" : "=l"(r) : "l"(a), "l"(b));
    return r;
}
__device__ __forceinline__ ull fma_f32x2(ull a, ull b, ull c) {
    ull r;
    asm("fma.rn.f32x2 %0, %1, %2, %3;" : "=l"(r) : "l"(a), "l"(b), "l"(c));
    return r;
}
__device__ __forceinline__ ull pack_dup(float p) {
    ull r;
    asm("mov.b64 %0, {%1, %1};" : "=l"(r) : "r"(__float_as_uint(p)));
    return r;
}

#define ABS2_MASK 0x7FFFFFFF7FFFFFFFULL

__global__ __launch_bounds__(QTILE)
void attn_partial(const float* __restrict__ q, const float* __restrict__ k,
                  const float* __restrict__ v, const int* __restrict__ mask)
{
    const int b = blockIdx.z;
    const int split = blockIdx.y;
    const int tid = threadIdx.x;
    const int qi = blockIdx.x * QTILE + tid;

    __shared__ __align__(16) float ks[KCHUNK][DD];
    __shared__ __align__(16) float vs[KCHUNK][DV];
    __shared__ float ms[KCHUNK];
    __shared__ __align__(16) float k0s[DD];

    // cooperative loads of this split's K/V chunk + mask + global k0 row
    const float* kbase = k + ((size_t)b * SK + (size_t)split * KCHUNK) * DD;
    const float* vbase = v + ((size_t)b * SK + (size_t)split * KCHUNK) * DV;
    for (int i = tid; i < KCHUNK * DD / 4; i += QTILE) {
        ((float4*)&ks[0][0])[i] = ((const float4*)kbase)[i];
        ((float4*)&vs[0][0])[i] = ((const float4*)vbase)[i];
    }
    if (tid < KCHUNK) ms[tid] = (float)mask[(size_t)b * SK + (size_t)split * KCHUNK + tid];
    if (tid < DD / 4) ((float4*)k0s)[tid] = ((const float4*)(k + (size_t)b * SK * DD))[tid];

    // load this thread's q row, negated, as packed f32x2
    ull qn[DD / 2];
    const float* qrow = q + ((size_t)b * SQ + qi) * DD;
#pragma unroll
    for (int i = 0; i < DD / 4; i++) {
        float4 t = ((const float4*)qrow)[i];
        float2 a = make_float2(-t.x, -t.y);
        float2 c = make_float2(-t.z, -t.w);
        qn[2 * i]     = *(ull*)&a;
        qn[2 * i + 1] = *(ull*)&c;
    }
    __syncthreads();

    // reference point: dist0 = L1(q, k[b][0]); shared by all splits so the
    // combine kernel can just sum partials (no per-split max bookkeeping).
    float dist0;
    {
        ull s0 = 0ULL, s1 = 0ULL;
        const ull* k0p = (const ull*)k0s;
#pragma unroll
        for (int i = 0; i < DD / 2; i += 2) {
            ull d0 = add_f32x2(k0p[i],     qn[i])     & ABS2_MASK;
            ull d1 = add_f32x2(k0p[i + 1], qn[i + 1]) & ABS2_MASK;
            s0 = add_f32x2(s0, d0);
            s1 = add_f32x2(s1, d1);
        }
        ull st = add_f32x2(s0, s1);
        float2 sf = *(float2*)&st;
        dist0 = sf.x + sf.y;
    }

    ull acc[DV / 2];
#pragma unroll
    for (int i = 0; i < DV / 2; i++) acc[i] = 0ULL;
    float lsum = 0.0f;

    for (int j = 0; j < KCHUNK; j++) {
        const ull* krow = (const ull*)&ks[j][0];
        ull s0 = 0ULL, s1 = 0ULL, s2 = 0ULL, s3 = 0ULL;
#pragma unroll
        for (int i = 0; i < DD / 2; i += 4) {
            ull d0 = add_f32x2(krow[i],     qn[i])     & ABS2_MASK;
            ull d1 = add_f32x2(krow[i + 1], qn[i + 1]) & ABS2_MASK;
            ull d2 = add_f32x2(krow[i + 2], qn[i + 2]) & ABS2_MASK;
            ull d3 = add_f32x2(krow[i + 3], qn[i + 3]) & ABS2_MASK;
            s0 = add_f32x2(s0, d0);
            s1 = add_f32x2(s1, d1);
            s2 = add_f32x2(s2, d2);
            s3 = add_f32x2(s3, d3);
        }
        ull st = add_f32x2(add_f32x2(s0, s1), add_f32x2(s2, s3));
        float2 sf = *(float2*)&st;
        float dist = sf.x + sf.y;

        // p = exp(score - m0) with score = -dist, m0 = -dist0; masked -> 0
        float p = __expf(dist0 - dist) * ms[j];
        lsum += p;
        ull pp = pack_dup(p);

        const ull* vrow = (const ull*)&vs[j][0];
#pragma unroll
        for (int i = 0; i < DV / 2; i++)
            acc[i] = fma_f32x2(vrow[i], pp, acc[i]);
    }

    // write partials: [b][split][d][q] so per-d stores are warp-coalesced
    float* pa = g_part_acc + (((size_t)b * NSPLIT + split) * DV) * SQ;
#pragma unroll
    for (int i = 0; i < DV / 2; i++) {
        float2 a = *(float2*)&acc[i];
        pa[(size_t)(2 * i) * SQ + qi]     = a.x;
        pa[(size_t)(2 * i + 1) * SQ + qi] = a.y;
    }
    g_part_l[((size_t)b * NSPLIT + split) * SQ + qi] = lsum;
}

__global__ void attn_combine(float* __restrict__ out)
{
    int idx = blockIdx.x * blockDim.x + threadIdx.x;  // over BB*DV*SQ
    if (idx >= BB * DV * SQ) return;
    int qi = idx & (SQ - 1);
    int d  = (idx >> 10) & (DV - 1);
    int b  = idx >> 16;

    float s = 0.0f, lt = 0.0f;
#pragma unroll
    for (int sp = 0; sp < NSPLIT; sp++) {
        s  += g_part_acc[(((size_t)b * NSPLIT + sp) * DV + d) * SQ + qi];
        lt += g_part_l[((size_t)b * NSPLIT + sp) * SQ + qi];
    }
    out[((size_t)b * SQ + qi) * DV + d] = s / lt;
}

extern "C" void kernel_launch(void* const* d_in, const int* in_sizes, int n_in,
                              void* d_out, int out_size)
{
    const float* q    = (const float*)d_in[0];
    const float* k    = (const float*)d_in[1];
    const float* v    = (const float*)d_in[2];
    const int*   mask = (const int*)d_in[3];
    float* out = (float*)d_out;

    dim3 grid(SQ / QTILE, NSPLIT, BB);
    attn_partial<<<grid, QTILE>>>(q, k, v, mask);

    int total = BB * DV * SQ;
    attn_combine<<<(total + 255) / 256, 256>>>(out);
}